// round 5
// baseline (speedup 1.0000x reference)
#include <cuda_runtime.h>

// MxCorrelation: out[b, (p+4)*9+(q+4), y, x] = (1/128) * sum_c a[b,c,y,x] * b[b,c,y+p,x+q]
// p,q in [-4,4], b zero-padded. in (8,128,128,128) f32, out (8,81,128,128) f32.
//
// R3: packed fp32 math via fma.rn.f32x2 (FFMA2) -- one fma-pipe slot, 2 FMAs.
//  - acc pairs (x0,x1)/(x2,x3) kept packed in u64 for the whole kernel
//  - even w-pairs free from ulonglong2 LDS; 5 odd pairs per window repacked (alu pipe)
//  - fill pipeline (cp.async double buffer) unchanged from R2

#define TY   4
#define CC   4
#define BR   (TY + 2)
#define BW   144               // 4 halo | 128 interior | 12 pad (16B-aligned rows)
#define NTHR 128
#define NCH  (128 / CC)
#define SBHALF (CC * BR * BW * 4)

typedef unsigned long long u64;

__device__ __forceinline__ u64 pkhl(u64 a, u64 b) {   // (hi(a), lo(b))
    u64 r;
    asm("{\n\t.reg .b32 al, ah, bl, bh;\n\t"
        "mov.b64 {al, ah}, %1;\n\t"
        "mov.b64 {bl, bh}, %2;\n\t"
        "mov.b64 %0, {ah, bl};\n\t}" : "=l"(r) : "l"(a), "l"(b));
    return r;
}
__device__ __forceinline__ void ffma2(u64& d, u64 a, u64 b) {
    asm("fma.rn.f32x2 %0, %1, %2, %0;" : "+l"(d) : "l"(a), "l"(b));
}
__device__ __forceinline__ u64 mul2(u64 a, u64 b) {
    u64 r; asm("mul.rn.f32x2 %0, %1, %2;" : "=l"(r) : "l"(a), "l"(b)); return r;
}
__device__ __forceinline__ u64 pk2(float a, float b) {
    u64 r; asm("mov.b64 %0, {%1, %2};" : "=l"(r) : "f"(a), "f"(b)); return r;
}

__global__ __launch_bounds__(NTHR, 3)
void corr_kernel(const float* __restrict__ A, const float* __restrict__ Bm,
                 float* __restrict__ O) {
    __shared__ __align__(16) float sB[2][CC][BR][BW];

    const int t  = threadIdx.x;
    const int xq = t & 31;
    const int yy = t >> 5;
    const int x0 = xq << 2;

    const int y0 = blockIdx.x * TY;
    const int p0 = (int)blockIdx.y * 3 - 4;
    const int bb = blockIdx.z;

    const float* Ab = A  + (size_t)bb * 2097152;
    const float* Bb = Bm + (size_t)bb * 2097152;

    // zero both buffers once (halo + invalid rows stay zero)
    float4* sB4 = (float4*)&sB[0][0][0][0];
#pragma unroll
    for (int i = 0; i < (2 * CC * BR * BW / 4) / NTHR + 1; i++) {
        int idx = t + i * NTHR;
        if (idx < 2 * CC * BR * BW / 4) sB4[idx] = make_float4(0.f, 0.f, 0.f, 0.f);
    }

    // hoisted fill descriptors: 6 interior float4 slots per thread
    const float* gptr[6];
    unsigned     sb0[6];
    bool         valid[6];
#pragma unroll
    for (int k = 0; k < 6; k++) {
        int idx = k * NTHR + t;
        int col = idx & 31;
        int row = idx >> 5;
        int c   = row / 6;
        int r   = row - c * 6;
        int gy  = y0 + p0 + r;
        valid[k] = (unsigned)gy < 128u;
        gptr[k]  = Bb + (size_t)c * 16384 + gy * 128 + col * 4;
        sb0[k]   = (unsigned)__cvta_generic_to_shared(&sB[0][c][r][4 + col * 4]);
    }
    __syncthreads();

    // prologue fill: chunk 0 -> buffer 0
#pragma unroll
    for (int k = 0; k < 6; k++) {
        if (valid[k])
            asm volatile("cp.async.cg.shared.global [%0], [%1], 16;\n"
                         :: "r"(sb0[k]), "l"(gptr[k]));
        gptr[k] += CC * 16384;
    }
    asm volatile("cp.async.commit_group;\n" ::: "memory");

    u64 acc[3][9][2];
#pragma unroll
    for (int pp = 0; pp < 3; pp++)
#pragma unroll
        for (int q = 0; q < 9; q++) { acc[pp][q][0] = 0ull; acc[pp][q][1] = 0ull; }

    const float* Arow = Ab + (y0 + yy) * 128 + x0;

    for (int chunk = 0; chunk < NCH; chunk++) {
        const int buf  = chunk & 1;
        const int nbuf = buf ^ 1;

        // prefetch A pairs: (x,y),(z,w) packed straight from the LDG.128
        ulonglong2 av[CC];
#pragma unroll
        for (int c = 0; c < CC; c++)
            av[c] = *(const ulonglong2*)(Arow + (size_t)(chunk * CC + c) * 16384);

        asm volatile("cp.async.wait_group 0;\n" ::: "memory");
        __syncthreads();

        if (chunk + 1 < NCH) {
#pragma unroll
            for (int k = 0; k < 6; k++) {
                if (valid[k])
                    asm volatile("cp.async.cg.shared.global [%0], [%1], 16;\n"
                                 :: "r"(sb0[k] + nbuf * SBHALF), "l"(gptr[k]));
                gptr[k] += CC * 16384;
            }
        }
        asm volatile("cp.async.commit_group;\n" ::: "memory");

        // compute: 4c x 3pp x (3 LDS.128 + 5 repack + 18 FFMA2)
#pragma unroll
        for (int c = 0; c < CC; c++) {
#pragma unroll
            for (int pp = 0; pp < 3; pp++) {
                const float* row = &sB[buf][c][yy + pp][0];
                ulonglong2 e0 = *(const ulonglong2*)(row + x0);       // (w0,w1)(w2,w3)
                ulonglong2 e1 = *(const ulonglong2*)(row + x0 + 4);   // (w4,w5)(w6,w7)
                ulonglong2 e2 = *(const ulonglong2*)(row + x0 + 8);   // (w8,w9)(w10,w11)
                u64 wp[11];
                wp[0] = e0.x;  wp[2] = e0.y;  wp[4] = e1.x;
                wp[6] = e1.y;  wp[8] = e2.x;  wp[10] = e2.y;
                wp[1] = pkhl(e0.x, e0.y);
                wp[3] = pkhl(e0.y, e1.x);
                wp[5] = pkhl(e1.x, e1.y);
                wp[7] = pkhl(e1.y, e2.x);
                wp[9] = pkhl(e2.x, e2.y);
#pragma unroll
                for (int q = 0; q < 9; q++) {
                    ffma2(acc[pp][q][0], av[c].x, wp[q]);       // x0,x1
                    ffma2(acc[pp][q][1], av[c].y, wp[q + 2]);   // x2,x3
                }
            }
        }
    }

    // epilogue: packed scale, 8B stores (16B-aligned base)
    const u64 s2 = pk2(1.0f / 128.0f, 1.0f / 128.0f);
    float* Ob = O + (size_t)bb * 81 * 16384;
#pragma unroll
    for (int pp = 0; pp < 3; pp++) {
        int dbase = (p0 + pp + 4) * 9;
#pragma unroll
        for (int q = 0; q < 9; q++) {
            size_t off = (size_t)(dbase + q) * 16384 + (y0 + yy) * 128 + x0;
            *(u64*)&Ob[off]     = mul2(acc[pp][q][0], s2);
            *(u64*)&Ob[off + 2] = mul2(acc[pp][q][1], s2);
        }
    }
}

extern "C" void kernel_launch(void* const* d_in, const int* in_sizes, int n_in,
                              void* d_out, int out_size) {
    const float* A = (const float*)d_in[0];
    const float* B = (const float*)d_in[1];
    float*       O = (float*)d_out;

    dim3 grid(32, 3, 8);
    corr_kernel<<<grid, NTHR>>>(A, B, O);
}

// round 6
// speedup vs baseline: 1.1517x; 1.1517x over previous
#include <cuda_runtime.h>

// MxCorrelation: out[b, (p+4)*9+(q+4), y, x] = (1/128) * sum_c a[b,c,y,x] * b[b,c,y+p,x+q]
// p,q in [-4,4], b zero-padded. in (8,128,128,128) f32, out (8,81,128,128) f32.
//
// R6: scalar FFMA mainloop (R2, reverting failed FFMA2) + persistent blocks with
// dynamic tile stealing to kill wave-quantization stragglers.
//  - grid = 456 workers (152 SM x 3 resident, exactly one wave)
//  - 768 tiles (32 ytile x 3 pgroup x 8 batch) pulled via global atomic counter
//  - pgroup-fastest decode: consecutive tiles share A rows / overlap B rows in L2
//  - halo columns zeroed once; stale invalid rows re-zeroed per tile (edge tiles only)
//  - cp.async double-buffered sB fill, 1 barrier per chunk, scalar float4 compute

#define TY   4
#define CC   4
#define BR   (TY + 2)
#define BW   144               // 4 halo | 128 interior | 12 pad
#define NTHR 128
#define NCH  (128 / CC)
#define NTILES (32 * 3 * 8)
#define NWORK  456
#define SBHALF (CC * BR * BW * 4)

__device__ int g_tile_ctr;

__global__ void reset_kernel() { g_tile_ctr = 0; }

__global__ __launch_bounds__(NTHR, 3)
void corr_kernel(const float* __restrict__ A, const float* __restrict__ Bm,
                 float* __restrict__ O) {
    __shared__ __align__(16) float sB[2][CC][BR][BW];
    __shared__ int s_tile;

    const int t  = threadIdx.x;
    const int xq = t & 31;
    const int yy = t >> 5;
    const int x0 = xq << 2;

    // zero both buffers once (halo + pad stay zero forever)
    float4* sB4 = (float4*)&sB[0][0][0][0];
#pragma unroll
    for (int i = 0; i < (2 * CC * BR * BW / 4) / NTHR + 1; i++) {
        int idx = t + i * NTHR;
        if (idx < 2 * CC * BR * BW / 4) sB4[idx] = make_float4(0.f, 0.f, 0.f, 0.f);
    }

    // per-thread fill-slot geometry (tile-independent parts)
    int col_[6], c_[6], r_[6];
    unsigned sb0[6];
#pragma unroll
    for (int k = 0; k < 6; k++) {
        int idx = k * NTHR + t;
        col_[k] = idx & 31;
        int row = idx >> 5;
        c_[k] = row / 6;
        r_[k] = row - c_[k] * 6;
        sb0[k] = (unsigned)__cvta_generic_to_shared(&sB[0][c_[k]][r_[k]][4 + col_[k] * 4]);
    }

    while (true) {
        if (t == 0) s_tile = atomicAdd(&g_tile_ctr, 1);
        __syncthreads();              // also orders smem zero/reuse vs refill
        const int tile = s_tile;
        if (tile >= NTILES) break;

        // decode: pgroup fastest (A reuse), then ytile, then batch
        const int pg = tile % 3;
        const int tmp = tile / 3;
        const int yt = tmp & 31;
        const int bb = tmp >> 5;

        const int y0 = yt * TY;
        const int p0 = pg * 3 - 4;

        const float* Ab = A  + (size_t)bb * 2097152;
        const float* Bb = Bm + (size_t)bb * 2097152;

        // per-tile fill descriptors
        const float* gptr[6];
        bool valid[6];
#pragma unroll
        for (int k = 0; k < 6; k++) {
            int gy   = y0 + p0 + r_[k];
            valid[k] = (unsigned)gy < 128u;
            gptr[k]  = Bb + (size_t)c_[k] * 16384 + gy * 128 + col_[k] * 4;
            if (!valid[k]) {   // stale data from a previous tile: zero both buffers
                asm volatile("st.shared.v4.b32 [%0], {%1,%1,%1,%1};" :: "r"(sb0[k]), "r"(0));
                asm volatile("st.shared.v4.b32 [%0], {%1,%1,%1,%1};" :: "r"(sb0[k] + (unsigned)SBHALF), "r"(0));
            }
        }

        // prologue fill: chunk 0 -> buffer 0
#pragma unroll
        for (int k = 0; k < 6; k++) {
            if (valid[k])
                asm volatile("cp.async.cg.shared.global [%0], [%1], 16;\n"
                             :: "r"(sb0[k]), "l"(gptr[k]));
            gptr[k] += CC * 16384;
        }
        asm volatile("cp.async.commit_group;\n" ::: "memory");

        float acc[3][9][4];
#pragma unroll
        for (int pp = 0; pp < 3; pp++)
#pragma unroll
            for (int q = 0; q < 9; q++)
#pragma unroll
                for (int j = 0; j < 4; j++) acc[pp][q][j] = 0.0f;

        const float* Arow = Ab + (y0 + yy) * 128 + x0;

        for (int chunk = 0; chunk < NCH; chunk++) {
            const int buf  = chunk & 1;
            const int nbuf = buf ^ 1;

            float4 av[CC];
#pragma unroll
            for (int c = 0; c < CC; c++)
                av[c] = *(const float4*)(Arow + (size_t)(chunk * CC + c) * 16384);

            asm volatile("cp.async.wait_group 0;\n" ::: "memory");
            __syncthreads();

            if (chunk + 1 < NCH) {
#pragma unroll
                for (int k = 0; k < 6; k++) {
                    if (valid[k])
                        asm volatile("cp.async.cg.shared.global [%0], [%1], 16;\n"
                                     :: "r"(sb0[k] + nbuf * (unsigned)SBHALF), "l"(gptr[k]));
                    gptr[k] += CC * 16384;
                }
            }
            asm volatile("cp.async.commit_group;\n" ::: "memory");

            // 4c x 3pp x (3 LDS.128 + 36 scalar FFMA)
#pragma unroll
            for (int c = 0; c < CC; c++) {
#pragma unroll
                for (int pp = 0; pp < 3; pp++) {
                    const float* row = &sB[buf][c][yy + pp][0];
                    float w[12];
                    *(float4*)&w[0] = *(const float4*)&row[x0];
                    *(float4*)&w[4] = *(const float4*)&row[x0 + 4];
                    *(float4*)&w[8] = *(const float4*)&row[x0 + 8];
#pragma unroll
                    for (int q = 0; q < 9; q++) {
                        acc[pp][q][0] += av[c].x * w[q];
                        acc[pp][q][1] += av[c].y * w[q + 1];
                        acc[pp][q][2] += av[c].z * w[q + 2];
                        acc[pp][q][3] += av[c].w * w[q + 3];
                    }
                }
            }
        }

        // epilogue: scale, float4 coalesced stores
        const float scale = 1.0f / 128.0f;
        float* Ob = O + (size_t)bb * 81 * 16384;
#pragma unroll
        for (int pp = 0; pp < 3; pp++) {
            int dbase = (p0 + pp + 4) * 9;
#pragma unroll
            for (int q = 0; q < 9; q++) {
                float4 v;
                v.x = acc[pp][q][0] * scale;
                v.y = acc[pp][q][1] * scale;
                v.z = acc[pp][q][2] * scale;
                v.w = acc[pp][q][3] * scale;
                *(float4*)&Ob[(size_t)(dbase + q) * 16384 + (y0 + yy) * 128 + x0] = v;
            }
        }
    }
}

extern "C" void kernel_launch(void* const* d_in, const int* in_sizes, int n_in,
                              void* d_out, int out_size) {
    const float* A = (const float*)d_in[0];
    const float* B = (const float*)d_in[1];
    float*       O = (float*)d_out;

    reset_kernel<<<1, 1>>>();
    corr_kernel<<<NWORK, NTHR>>>(A, B, O);
}